// round 2
// baseline (speedup 1.0000x reference)
#include <cuda_runtime.h>
#include <cuda_bf16.h>
#include <math.h>

#define BB 2
#define LL 1024
#define DD 512
#define HH 8
#define HD 64
#define KK 24
#define KD (KK*DD)   // 12288
#define EPSV 1e-5f

// ---------------- scratch (static device globals; no allocation) ----------------
__device__ float g_xtcat[(size_t)BB*LL*KD];   // 100.7 MB conv output, (b,l, k*D+d)
__device__ float g_xt[BB*LL*DD];
__device__ float g_q[BB*LL*DD];
__device__ float g_k[BB*LL*DD];
__device__ float g_v[BB*LL*DD];
__device__ float g_gates[BB*HH*LL];
__device__ float g_cumg[BB*HH*LL];
__device__ float g_sim[BB*HH*LL];
__device__ float g_ao[BB*LL*DD];

// ---------------- 1) Toeplitz causal conv: out_k = T_k @ X_b ----------------
// grid: (D/128, L/128, B*K), block (16,16). 128x128 tile, BK=16, 8x8 micro.
__global__ void __launch_bounds__(256)
conv_kernel(const float* __restrict__ x, const float* __restrict__ basis)
{
    __shared__ float sb[LL];
    __shared__ float As[16][128];
    __shared__ float Bs[16][128];
    const int b  = blockIdx.z / KK, kf = blockIdx.z % KK;
    const int lb = blockIdx.y * 128, db = blockIdx.x * 128;
    const int tx = threadIdx.x, ty = threadIdx.y;
    const int tid = ty * 16 + tx;
    const int nb = lb + 128;                 // t range: [0, lb+128)

    for (int i = tid; i < nb; i += 256) sb[i] = basis[i * KK + kf];
    __syncthreads();

    float acc[8][8];
#pragma unroll
    for (int r = 0; r < 8; ++r)
#pragma unroll
        for (int c = 0; c < 8; ++c) acc[r][c] = 0.f;

    const int lA = tid >> 1;                 // 0..127
    const int tbase = (tid & 1) * 8;         // 0 or 8

    for (int t0 = 0; t0 < nb; t0 += 16) {
        // Build Toeplitz A tile: As[tt][l] = basis[(lb+l)-(t0+tt)] (0 if acausal)
        {
            const int lg = lb + lA;
#pragma unroll
            for (int j = 0; j < 8; ++j) {
                int tg = t0 + tbase + j;
                As[tbase + j][lA] = (lg >= tg) ? sb[lg - tg] : 0.f;
            }
        }
        // Load X tile
#pragma unroll
        for (int it = 0; it < 2; ++it) {
            int i = tid + it * 256;          // 0..511
            int tt = i >> 5, d4 = (i & 31) * 4;
            *(float4*)&Bs[tt][d4] =
                *(const float4*)&x[((size_t)(b * LL + t0 + tt)) * DD + db + d4];
        }
        __syncthreads();
#pragma unroll
        for (int tt = 0; tt < 16; ++tt) {
            float4 a0 = *(float4*)&As[tt][ty * 4];
            float4 a1 = *(float4*)&As[tt][ty * 4 + 64];
            float4 b0 = *(float4*)&Bs[tt][tx * 4];
            float4 b1 = *(float4*)&Bs[tt][tx * 4 + 64];
            float ar[8] = {a0.x,a0.y,a0.z,a0.w,a1.x,a1.y,a1.z,a1.w};
            float br[8] = {b0.x,b0.y,b0.z,b0.w,b1.x,b1.y,b1.z,b1.w};
#pragma unroll
            for (int r = 0; r < 8; ++r)
#pragma unroll
                for (int c = 0; c < 8; ++c) acc[r][c] += ar[r] * br[c];
        }
        __syncthreads();
    }
#pragma unroll
    for (int r = 0; r < 8; ++r) {
        int lg = lb + ((r < 4) ? ty * 4 + r : 64 + ty * 4 + (r - 4));
        size_t base = (size_t)(b * LL + lg) * KD + kf * DD + db;
        float4 o0 = {acc[r][0], acc[r][1], acc[r][2], acc[r][3]};
        float4 o1 = {acc[r][4], acc[r][5], acc[r][6], acc[r][7]};
        *(float4*)&g_xtcat[base + tx * 4]      = o0;
        *(float4*)&g_xtcat[base + 64 + tx * 4] = o1;
    }
}

// ---------------- 2) generic fp32 GEMM + bias: C = A(M,Kd) @ W(Kd,N) + bias ----------------
// grid: (N/64, M/128), block (16,16). BM=128, BN=64, BK=16, 8x4 micro.
__global__ void __launch_bounds__(256)
gemm128x64(const float* __restrict__ A, const float* __restrict__ W,
           const float* __restrict__ bias, float* __restrict__ C,
           int M, int N, int Kd)
{
    __shared__ float As[16][128];
    __shared__ float Bs[16][64];
    const int tx = threadIdx.x, ty = threadIdx.y;
    const int tid = ty * 16 + tx;
    const int row0 = blockIdx.y * 128, col0 = blockIdx.x * 64;

    float acc[8][4];
#pragma unroll
    for (int r = 0; r < 8; ++r)
#pragma unroll
        for (int c = 0; c < 4; ++c) acc[r][c] = 0.f;

    const int mA = tid >> 1, kbase = (tid & 1) * 8;
    const int kkB = tid >> 4, n4 = (tid & 15) * 4;

    for (int k0 = 0; k0 < Kd; k0 += 16) {
        const float* ap = &A[(size_t)(row0 + mA) * Kd + k0 + kbase];
        float4 a0 = *(const float4*)ap;
        float4 a1 = *(const float4*)(ap + 4);
        As[kbase + 0][mA] = a0.x; As[kbase + 1][mA] = a0.y;
        As[kbase + 2][mA] = a0.z; As[kbase + 3][mA] = a0.w;
        As[kbase + 4][mA] = a1.x; As[kbase + 5][mA] = a1.y;
        As[kbase + 6][mA] = a1.z; As[kbase + 7][mA] = a1.w;
        *(float4*)&Bs[kkB][n4] = *(const float4*)&W[(size_t)(k0 + kkB) * N + col0 + n4];
        __syncthreads();
#pragma unroll
        for (int kk = 0; kk < 16; ++kk) {
            float4 av0 = *(float4*)&As[kk][ty * 4];
            float4 av1 = *(float4*)&As[kk][ty * 4 + 64];
            float4 bv  = *(float4*)&Bs[kk][tx * 4];
            float ar[8] = {av0.x,av0.y,av0.z,av0.w,av1.x,av1.y,av1.z,av1.w};
            float br[4] = {bv.x,bv.y,bv.z,bv.w};
#pragma unroll
            for (int r = 0; r < 8; ++r)
#pragma unroll
                for (int c = 0; c < 4; ++c) acc[r][c] += ar[r] * br[c];
        }
        __syncthreads();
    }
    float4 bb = *(const float4*)&bias[col0 + tx * 4];
    float bcast[4] = {bb.x, bb.y, bb.z, bb.w};
#pragma unroll
    for (int r = 0; r < 8; ++r) {
        int row = row0 + ((r < 4) ? ty * 4 + r : 64 + ty * 4 + (r - 4));
        float4 o = {acc[r][0] + bcast[0], acc[r][1] + bcast[1],
                    acc[r][2] + bcast[2], acc[r][3] + bcast[3]};
        *(float4*)&C[(size_t)row * N + col0 + tx * 4] = o;
    }
}

// ---------------- 3) gate logits + sim: one block (64 thr) per (b,H,l) ----------------
__global__ void __launch_bounds__(64)
gates_kernel(const float* __restrict__ Wgz, const float* __restrict__ bgz,
             const float* __restrict__ kvs, const float* __restrict__ qks)
{
    const int idx = blockIdx.x;             // bh*L + l
    const int l  = idx & (LL - 1);
    const int bh = idx >> 10;
    const int b  = bh >> 3, hh = bh & 7;
    const size_t base = ((size_t)(b * LL + l)) * DD + hh * HD;
    const float* kp = g_k + base;
    const float* vp = g_v + base;
    const float* qp = g_q + base;
    const int j = threadIdx.x;

    float kj = kp[j];
    float w = 0.f;
#pragma unroll 8
    for (int i = 0; i < 64; ++i) w += vp[i] * Wgz[i * 64 + j];
    float p1 = w * kj;           // -> v^T M k
    float p2 = qp[j] * kj;       // -> q.k
#pragma unroll
    for (int off = 16; off; off >>= 1) {
        p1 += __shfl_down_sync(0xffffffffu, p1, off);
        p2 += __shfl_down_sync(0xffffffffu, p2, off);
    }
    __shared__ float r1[2], r2[2];
    if ((j & 31) == 0) { r1[j >> 5] = p1; r2[j >> 5] = p2; }
    __syncthreads();
    if (j == 0) {
        float s1 = r1[0] + r1[1], s2 = r2[0] + r2[1];
        float logit = kvs[0] * s1 + bgz[0];
        float o = (logit > 0.f) ? logit : 0.01f * logit;
        g_gates[idx] = o * o + EPSV;
        g_sim[idx]   = s2 * qks[hh];
    }
}

// ---------------- 4) inclusive scan of gates along L, per (b,H) ----------------
__global__ void __launch_bounds__(LL)
scan_kernel()
{
    __shared__ float s[LL];
    const int t = threadIdx.x;
    const int base = blockIdx.x * LL;
    s[t] = g_gates[base + t];
    __syncthreads();
#pragma unroll
    for (int off = 1; off < LL; off <<= 1) {
        float vv = (t >= off) ? s[t - off] : 0.f;
        __syncthreads();
        s[t] += vv;
        __syncthreads();
    }
    g_cumg[base + t] = s[t];
}

// ---------------- 5) causal linear attention + output gating ----------------
// grid: (L/64, B*H), block (16,16). 64x64 tiles over (l,t).
__global__ void __launch_bounds__(256)
attn_kernel(const float* __restrict__ Wg, const float* __restrict__ bg,
            const float* __restrict__ kvs)
{
    extern __shared__ float sm[];
    float* Qts = sm;                 // [64 d][68] transposed
    float* Kts = Qts + 64 * 68;      // [64 d][68] transposed
    float* Vs  = Kts + 64 * 68;      // [64 t][68]
    float* Sts = Vs  + 64 * 68;      // [64 t][68] scores transposed
    float* gsh = Sts + 64 * 68;      // [64]

    const int bh = blockIdx.y;
    const int b = bh >> 3, hh = bh & 7;
    const int lb = blockIdx.x * 64;
    const int tx = threadIdx.x, ty = threadIdx.y;
    const int tid = ty * 16 + tx;

    for (int i = tid; i < 1024; i += 256) {
        int l = i >> 4, d4 = (i & 15) * 4;
        float4 qv = *(const float4*)&g_q[((size_t)(b * LL + lb + l)) * DD + hh * HD + d4];
        Qts[(d4 + 0) * 68 + l] = qv.x;
        Qts[(d4 + 1) * 68 + l] = qv.y;
        Qts[(d4 + 2) * 68 + l] = qv.z;
        Qts[(d4 + 3) * 68 + l] = qv.w;
    }

    float acc2[4][4];
#pragma unroll
    for (int r = 0; r < 4; ++r)
#pragma unroll
        for (int c = 0; c < 4; ++c) acc2[r][c] = 0.f;

    for (int t0 = 0; t0 <= lb; t0 += 64) {
        for (int i = tid; i < 1024; i += 256) {
            int t = i >> 4, d4 = (i & 15) * 4;
            size_t gidx = ((size_t)(b * LL + t0 + t)) * DD + hh * HD + d4;
            float4 kv = *(const float4*)&g_k[gidx];
            float4 vv = *(const float4*)&g_v[gidx];
            Kts[(d4 + 0) * 68 + t] = kv.x;
            Kts[(d4 + 1) * 68 + t] = kv.y;
            Kts[(d4 + 2) * 68 + t] = kv.z;
            Kts[(d4 + 3) * 68 + t] = kv.w;
            *(float4*)&Vs[t * 68 + d4] = vv;
        }
        if (tid < 64) gsh[tid] = g_gates[bh * LL + t0 + tid];
        __syncthreads();

        // scores = Q K^T
        float acc1[4][4];
#pragma unroll
        for (int r = 0; r < 4; ++r)
#pragma unroll
            for (int c = 0; c < 4; ++c) acc1[r][c] = 0.f;
#pragma unroll 8
        for (int d = 0; d < 64; ++d) {
            float4 aq = *(float4*)&Qts[d * 68 + ty * 4];
            float4 ak = *(float4*)&Kts[d * 68 + tx * 4];
            float qa[4] = {aq.x, aq.y, aq.z, aq.w};
            float ka[4] = {ak.x, ak.y, ak.z, ak.w};
#pragma unroll
            for (int r = 0; r < 4; ++r)
#pragma unroll
                for (int c = 0; c < 4; ++c) acc1[r][c] += qa[r] * ka[c];
        }
        // mask + gate weight, store transposed for second GEMM
#pragma unroll
        for (int c = 0; c < 4; ++c) {
            int tg = t0 + tx * 4 + c;
            float gg = gsh[tx * 4 + c];
#pragma unroll
            for (int r = 0; r < 4; ++r) {
                int lg = lb + ty * 4 + r;
                Sts[(tx * 4 + c) * 68 + ty * 4 + r] = (tg <= lg) ? acc1[r][c] * gg : 0.f;
            }
        }
        __syncthreads();
        // ctxt += S @ V
#pragma unroll 8
        for (int t = 0; t < 64; ++t) {
            float4 as = *(float4*)&Sts[t * 68 + ty * 4];
            float4 av = *(float4*)&Vs[t * 68 + tx * 4];
            float sa[4] = {as.x, as.y, as.z, as.w};
            float va[4] = {av.x, av.y, av.z, av.w};
#pragma unroll
            for (int r = 0; r < 4; ++r)
#pragma unroll
                for (int c = 0; c < 4; ++c) acc2[r][c] += sa[r] * va[c];
        }
        __syncthreads();
    }

    const float s = kvs[0];
#pragma unroll
    for (int r = 0; r < 4; ++r) {
        int lg = lb + ty * 4 + r;
        float cg = g_cumg[bh * LL + lg] + EPSV;
        float simv = g_sim[bh * LL + lg];
        float inv = s / cg;
        float4 o;
        float* oc = (float*)&o;
#pragma unroll
        for (int c = 0; c < 4; ++c) {
            int ii = tx * 4 + c;
            float gate = 1.f / (1.f + expf(-(simv * Wg[ii] + bg[ii])));
            oc[c] = acc2[r][c] * inv * gate;
        }
        *(float4*)&g_ao[((size_t)(b * LL + lg)) * DD + hh * HD + tx * 4] = o;
    }
}

// ---------------- launch ----------------
extern "C" void kernel_launch(void* const* d_in, const int* in_sizes, int n_in,
                              void* d_out, int out_size)
{
    (void)in_sizes; (void)n_in; (void)out_size;
    const float* x     = (const float*)d_in[0];
    const float* basis = (const float*)d_in[1];
    const float* Wq    = (const float*)d_in[2];
    const float* bq    = (const float*)d_in[3];
    const float* Wk    = (const float*)d_in[4];
    const float* bk    = (const float*)d_in[5];
    const float* Wv    = (const float*)d_in[6];
    const float* bv    = (const float*)d_in[7];
    const float* Wo    = (const float*)d_in[8];
    const float* bo    = (const float*)d_in[9];
    const float* Wm    = (const float*)d_in[10];
    const float* bm    = (const float*)d_in[11];
    const float* Wgz   = (const float*)d_in[12];
    const float* bgz   = (const float*)d_in[13];
    const float* Wg    = (const float*)d_in[14];
    const float* bg    = (const float*)d_in[15];
    const float* kvs   = (const float*)d_in[16];
    const float* qks   = (const float*)d_in[17];

    float *xtcat, *xt, *q, *k, *v, *ao;
    cudaGetSymbolAddress((void**)&xtcat, g_xtcat);
    cudaGetSymbolAddress((void**)&xt, g_xt);
    cudaGetSymbolAddress((void**)&q,  g_q);
    cudaGetSymbolAddress((void**)&k,  g_k);
    cudaGetSymbolAddress((void**)&v,  g_v);
    cudaGetSymbolAddress((void**)&ao, g_ao);

    dim3 blk(16, 16);
    const int M = BB * LL;  // 2048

    // 1) spectral conv -> xtcat
    conv_kernel<<<dim3(DD / 128, LL / 128, BB * KK), blk>>>(x, basis);
    // 2) xt = xtcat @ Wm + bm
    gemm128x64<<<dim3(DD / 64, M / 128), blk>>>(xtcat, Wm, bm, xt, M, DD, KD);
    // 3) q/k/v
    gemm128x64<<<dim3(DD / 64, M / 128), blk>>>(x,  Wq, bq, q, M, DD, DD);
    gemm128x64<<<dim3(DD / 64, M / 128), blk>>>(xt, Wk, bk, k, M, DD, DD);
    gemm128x64<<<dim3(DD / 64, M / 128), blk>>>(xt, Wv, bv, v, M, DD, DD);
    // 4) gates + sim
    gates_kernel<<<BB * HH * LL, 64>>>(Wgz, bgz, kvs, qks);
    // 5) cumulative gate sums
    scan_kernel<<<BB * HH, LL>>>();
    // 6) attention + output gate
    const int attn_smem = (4 * 64 * 68 + 64) * (int)sizeof(float);
    cudaFuncSetAttribute(attn_kernel, cudaFuncAttributeMaxDynamicSharedMemorySize, attn_smem);
    attn_kernel<<<dim3(LL / 64, BB * HH), blk, attn_smem>>>(Wg, bg, kvs);
    // 7) out = ao @ Wo + bo
    gemm128x64<<<dim3(DD / 64, M / 128), blk>>>(ao, Wo, bo, (float*)d_out, M, DD, DD);
}

// round 5
// speedup vs baseline: 2.0601x; 2.0601x over previous
#include <cuda_runtime.h>
#include <cuda_bf16.h>
#include <math.h>
#include <stdint.h>

#define BB 2
#define LL 1024
#define DD 512
#define HH 8
#define HD 64
#define KK 24
#define KD (KK*DD)   // 12288
#define MM (BB*LL)   // 2048
#define EPSV 1e-5f

// ================= scratch (static device globals; no allocation) =================
__device__ __nv_bfloat16 g_xtc_hi[(size_t)MM*KD];   // conv output hi (50 MB)
__device__ __nv_bfloat16 g_xtc_lo[(size_t)MM*KD];
__device__ __nv_bfloat16 g_toep_hi[(size_t)KK*32*4096];  // Toeplitz tile table
__device__ __nv_bfloat16 g_toep_lo[(size_t)KK*32*4096];
__device__ __nv_bfloat16 g_xT_hi[BB*DD*LL], g_xT_lo[BB*DD*LL];  // x^T (b,d,l)
__device__ __nv_bfloat16 g_x_hi[MM*DD],  g_x_lo[MM*DD];         // x row-major
__device__ __nv_bfloat16 g_WmT_hi[DD*KD], g_WmT_lo[DD*KD];
__device__ __nv_bfloat16 g_WqT_hi[DD*DD], g_WqT_lo[DD*DD];
__device__ __nv_bfloat16 g_WkT_hi[DD*DD], g_WkT_lo[DD*DD];
__device__ __nv_bfloat16 g_WvT_hi[DD*DD], g_WvT_lo[DD*DD];
__device__ __nv_bfloat16 g_WoT_hi[DD*DD], g_WoT_lo[DD*DD];
__device__ __nv_bfloat16 g_xt_hi[MM*DD], g_xt_lo[MM*DD];
__device__ __nv_bfloat16 g_ao_hi[MM*DD], g_ao_lo[MM*DD];
__device__ float g_q[MM*DD];
__device__ float g_k[MM*DD];
__device__ float g_v[MM*DD];
__device__ float g_gates[BB*HH*LL];
__device__ float g_cumg[BB*HH*LL];
__device__ float g_sim[BB*HH*LL];

// ================= PTX helpers (base ISA only: sm_80-class) =================
__device__ __forceinline__ uint32_t smem_u32(const void* p) {
    uint32_t a;
    asm("{ .reg .u64 t; cvta.to.shared.u64 t, %1; cvt.u32.u64 %0, t; }" : "=r"(a) : "l"(p));
    return a;
}
__device__ __forceinline__ void cp16(uint32_t dst, const void* src) {
    asm volatile("cp.async.cg.shared.global [%0], [%1], 16;" :: "r"(dst), "l"(src));
}
#define CP_COMMIT() asm volatile("cp.async.commit_group;" ::: "memory")
#define CP_WAIT(n)  asm volatile("cp.async.wait_group %0;" :: "n"(n) : "memory")

__device__ __forceinline__ void ldm4(uint32_t a, uint32_t r[4]) {
    asm volatile("ldmatrix.sync.aligned.m8n8.x4.shared.b16 {%0,%1,%2,%3}, [%4];"
                 : "=r"(r[0]), "=r"(r[1]), "=r"(r[2]), "=r"(r[3]) : "r"(a));
}
__device__ __forceinline__ void mma16816(float c[4], const uint32_t a[4], uint32_t b0, uint32_t b1) {
    asm volatile("mma.sync.aligned.m16n8k16.row.col.f32.bf16.bf16.f32 "
                 "{%0,%1,%2,%3}, {%4,%5,%6,%7}, {%8,%9}, {%0,%1,%2,%3};"
                 : "+f"(c[0]), "+f"(c[1]), "+f"(c[2]), "+f"(c[3])
                 : "r"(a[0]), "r"(a[1]), "r"(a[2]), "r"(a[3]), "r"(b0), "r"(b1));
}
__device__ __forceinline__ uint32_t split_pack(float f0, float f1, uint32_t& lopack) {
    __nv_bfloat16 h0 = __float2bfloat16(f0);
    __nv_bfloat16 h1 = __float2bfloat16(f1);
    __nv_bfloat16 l0 = __float2bfloat16(f0 - __bfloat162float(h0));
    __nv_bfloat16 l1 = __float2bfloat16(f1 - __bfloat162float(h1));
    lopack = (uint32_t)__bfloat16_as_ushort(l0) | ((uint32_t)__bfloat16_as_ushort(l1) << 16);
    return (uint32_t)__bfloat16_as_ushort(h0) | ((uint32_t)__bfloat16_as_ushort(h1) << 16);
}

// ---- smem layout per pipeline stage (BM=128, BN=64, BK=32, pad to 40 bf16/row) ----
#define ROWB 80           // bytes per padded row
#define OFF_AH 0
#define OFF_AL 10240
#define OFF_BH 20480
#define OFF_BL 25600
#define STG_BYTES 30720
#define MMA_SMEM (2*STG_BYTES)

// Load one stage: A 128x32 (hi+lo), B 64x32 (hi+lo). 256 threads.
__device__ __forceinline__ void load_stage(uint32_t sb,
        const __nv_bfloat16* Ah, const __nv_bfloat16* Al, size_t sA,
        const __nv_bfloat16* Bh, const __nv_bfloat16* Bl, size_t sB, int tid) {
#pragma unroll
    for (int i = 0; i < 2; ++i) {
        int idx = tid + i * 256;               // 0..511: A chunks
        int row = idx >> 2, c = idx & 3;
        uint32_t d = sb + (uint32_t)row * ROWB + (uint32_t)c * 16;
        cp16(d + OFF_AH, Ah + (size_t)row * sA + c * 8);
        cp16(d + OFF_AL, Al + (size_t)row * sA + c * 8);
    }
    {
        int row = tid >> 2, c = tid & 3;       // 256 B chunks
        uint32_t d = sb + (uint32_t)row * ROWB + (uint32_t)c * 16;
        cp16(d + OFF_BH, Bh + (size_t)row * sB + c * 8);
        cp16(d + OFF_BL, Bl + (size_t)row * sB + c * 8);
    }
}

// Compute one stage: 48 mma/warp (3-term split). Warp grid 4x2 (M x N), warp tile 32x32.
__device__ __forceinline__ void compute_stage(uint32_t sb, float acc[2][4][4],
                                              int wm, int wn, int lane) {
    const int t8 = lane & 7, sub = lane >> 3;
    const int arow = wm * 32 + (sub & 1) * 8 + t8;
    const int nrow = wn * 32 + (sub & 1) * 8 + t8;
    const int koff = (sub >> 1) * 8;
#pragma unroll
    for (int kh = 0; kh < 2; ++kh) {
        const int kc = kh * 16;
        uint32_t ah[2][4], al[2][4], bh[2][4], bl[2][4];
#pragma unroll
        for (int mt = 0; mt < 2; ++mt) {
            uint32_t off = (uint32_t)(arow + mt * 16) * ROWB + (uint32_t)(kc + koff) * 2;
            ldm4(sb + OFF_AH + off, ah[mt]);
            ldm4(sb + OFF_AL + off, al[mt]);
        }
#pragma unroll
        for (int nt = 0; nt < 2; ++nt) {
            uint32_t off = (uint32_t)(nrow + nt * 16) * ROWB + (uint32_t)(kc + koff) * 2;
            ldm4(sb + OFF_BH + off, bh[nt]);
            ldm4(sb + OFF_BL + off, bl[nt]);
        }
#pragma unroll
        for (int mt = 0; mt < 2; ++mt)
#pragma unroll
            for (int n8 = 0; n8 < 4; ++n8) {
                int nt = n8 >> 1, sl = n8 & 1;
                mma16816(acc[mt][n8], ah[mt], bh[nt][sl], bh[nt][sl + 2]);
                mma16816(acc[mt][n8], ah[mt], bl[nt][sl], bl[nt][sl + 2]);
                mma16816(acc[mt][n8], al[mt], bh[nt][sl], bh[nt][sl + 2]);
            }
    }
}

// ================= Toeplitz tile table precompute =================
// tile (kf, j): 128x32, A[r][c] = basis[r - c + (j-3)*32, kf] (0 if out of range)
__global__ void __launch_bounds__(256)
toep_prep(const float* __restrict__ basis) {
    int tile = blockIdx.x;                 // kf*32 + j
    int kf = tile >> 5, j = tile & 31;
    int d0 = (j - 3) * 32;
    size_t base = (size_t)tile * 4096;
    for (int idx = threadIdx.x; idx < 4096; idx += 256) {
        int r = idx >> 5, c = idx & 31;
        int off = r - c + d0;
        float v = (off >= 0 && off < LL) ? basis[off * KK + kf] : 0.f;
        __nv_bfloat16 h = __float2bfloat16(v);
        g_toep_hi[base + idx] = h;
        g_toep_lo[base + idx] = __float2bfloat16(v - __bfloat162float(h));
    }
}

// ================= prep kernels =================
__global__ void __launch_bounds__(256)
trans_split(const float* __restrict__ in, __nv_bfloat16* __restrict__ hi,
            __nv_bfloat16* __restrict__ lo, int R, int C) {
    __shared__ float t[32][33];
    int rb = blockIdx.y * 32, cb = blockIdx.x * 32, bz = blockIdx.z;
    const float* src = in + (size_t)bz * R * C;
    int tx = threadIdx.x, ty = threadIdx.y;   // (32, 8)
#pragma unroll
    for (int i = 0; i < 32; i += 8)
        t[ty + i][tx] = src[(size_t)(rb + ty + i) * C + cb + tx];
    __syncthreads();
    size_t ob = (size_t)bz * R * C;
#pragma unroll
    for (int i = 0; i < 32; i += 8) {
        float v = t[tx][ty + i];
        __nv_bfloat16 h = __float2bfloat16(v);
        size_t o = ob + (size_t)(cb + ty + i) * R + rb + tx;
        hi[o] = h;
        lo[o] = __float2bfloat16(v - __bfloat162float(h));
    }
}

__global__ void __launch_bounds__(256)
split_only(const float* __restrict__ in, __nv_bfloat16* __restrict__ hi,
           __nv_bfloat16* __restrict__ lo, int n) {
    int i = blockIdx.x * 256 + threadIdx.x;
    if (i < n) {
        float v = in[i];
        __nv_bfloat16 h = __float2bfloat16(v);
        hi[i] = h;
        lo[i] = __float2bfloat16(v - __bfloat162float(h));
    }
}

// ================= conv via mma.sync (Toeplitz-table GEMM) =================
// grid: (D/64, L/128, B*K). out[b*L+l, kf*D + d], split bf16.
__global__ void __launch_bounds__(256)
conv_mma() {
    extern __shared__ char dsm[];
    uint32_t sb0 = smem_u32(dsm);
    const int tid = threadIdx.x, wid = tid >> 5, lane = tid & 31;
    const int wm = wid >> 1, wn = wid & 1;
    const int db = blockIdx.x * 64;
    const int y = blockIdx.y, lb = y * 128;
    const int b = blockIdx.z / KK, kf = blockIdx.z % KK;
    const int nc = 4 * (y + 1);

    const __nv_bfloat16* xh = g_xT_hi + (size_t)b * DD * LL + (size_t)db * LL;
    const __nv_bfloat16* xl = g_xT_lo + (size_t)b * DD * LL + (size_t)db * LL;

    float acc[2][4][4];
#pragma unroll
    for (int a = 0; a < 2; ++a)
#pragma unroll
        for (int n = 0; n < 4; ++n)
#pragma unroll
            for (int e = 0; e < 4; ++e) acc[a][n][e] = 0.f;

    // chunk c: A tile = toep(kf, 4y - c + 3), B = xT cols t0 = 32c
    {
        size_t toff = ((size_t)(kf * 32 + 4 * y + 3)) * 4096;
        load_stage(sb0, g_toep_hi + toff, g_toep_lo + toff, 32, xh, xl, LL, tid);
        CP_COMMIT();
    }
    for (int c = 0; c < nc; ++c) {
        if (c + 1 < nc) {
            size_t toff = ((size_t)(kf * 32 + 4 * y - (c + 1) + 3)) * 4096;
            int t0 = 32 * (c + 1);
            load_stage(sb0 + ((c + 1) & 1) * STG_BYTES,
                       g_toep_hi + toff, g_toep_lo + toff, 32, xh + t0, xl + t0, LL, tid);
            CP_COMMIT();
            CP_WAIT(1);
        } else {
            CP_WAIT(0);
        }
        __syncthreads();
        compute_stage(sb0 + (c & 1) * STG_BYTES, acc, wm, wn, lane);
        __syncthreads();
    }

    // epilogue: split to hi/lo, 4B stores
    const int g = lane >> 2, tq = lane & 3;
#pragma unroll
    for (int mt = 0; mt < 2; ++mt) {
#pragma unroll
        for (int n8 = 0; n8 < 4; ++n8) {
            int col = db + wn * 32 + n8 * 8 + tq * 2;
            int r0 = lb + wm * 32 + mt * 16 + g;
            size_t o0 = (size_t)(b * LL + r0) * KD + (size_t)kf * DD + col;
            size_t o1 = o0 + 8 * (size_t)KD;
            uint32_t lp;
            uint32_t hp = split_pack(acc[mt][n8][0], acc[mt][n8][1], lp);
            *(uint32_t*)&g_xtc_hi[o0] = hp;  *(uint32_t*)&g_xtc_lo[o0] = lp;
            hp = split_pack(acc[mt][n8][2], acc[mt][n8][3], lp);
            *(uint32_t*)&g_xtc_hi[o1] = hp;  *(uint32_t*)&g_xtc_lo[o1] = lp;
        }
    }
}

// ================= generic split-bf16 GEMM via mma.sync =================
// C[m0+128, n0+64] = A[M,Kd] * B[Nout,Kd]^T + bias. grid (Nout/64, M/128).
__global__ void __launch_bounds__(256)
gemm_mma(const __nv_bfloat16* __restrict__ Ahi, const __nv_bfloat16* __restrict__ Alo,
         const __nv_bfloat16* __restrict__ Bhi, const __nv_bfloat16* __restrict__ Blo,
         const float* __restrict__ bias, float* __restrict__ Cf,
         __nv_bfloat16* __restrict__ Chi, __nv_bfloat16* __restrict__ Clo,
         int Kd, int Nout) {
    extern __shared__ char dsm[];
    uint32_t sb0 = smem_u32(dsm);
    const int tid = threadIdx.x, wid = tid >> 5, lane = tid & 31;
    const int wm = wid >> 1, wn = wid & 1;
    const int n0 = blockIdx.x * 64, m0 = blockIdx.y * 128;
    const int nc = Kd >> 5;

    const __nv_bfloat16* ah = Ahi + (size_t)m0 * Kd;
    const __nv_bfloat16* al = Alo + (size_t)m0 * Kd;
    const __nv_bfloat16* bh = Bhi + (size_t)n0 * Kd;
    const __nv_bfloat16* bl = Blo + (size_t)n0 * Kd;

    float acc[2][4][4];
#pragma unroll
    for (int a = 0; a < 2; ++a)
#pragma unroll
        for (int n = 0; n < 4; ++n)
#pragma unroll
            for (int e = 0; e < 4; ++e) acc[a][n][e] = 0.f;

    load_stage(sb0, ah, al, Kd, bh, bl, Kd, tid);
    CP_COMMIT();
    for (int c = 0; c < nc; ++c) {
        if (c + 1 < nc) {
            int k0 = 32 * (c + 1);
            load_stage(sb0 + ((c + 1) & 1) * STG_BYTES,
                       ah + k0, al + k0, Kd, bh + k0, bl + k0, Kd, tid);
            CP_COMMIT();
            CP_WAIT(1);
        } else {
            CP_WAIT(0);
        }
        __syncthreads();
        compute_stage(sb0 + (c & 1) * STG_BYTES, acc, wm, wn, lane);
        __syncthreads();
    }

    const int g = lane >> 2, tq = lane & 3;
#pragma unroll
    for (int mt = 0; mt < 2; ++mt) {
#pragma unroll
        for (int n8 = 0; n8 < 4; ++n8) {
            int col = n0 + wn * 32 + n8 * 8 + tq * 2;
            float b0v = bias[col], b1v = bias[col + 1];
            int r0 = m0 + wm * 32 + mt * 16 + g;
            float v00 = acc[mt][n8][0] + b0v, v01 = acc[mt][n8][1] + b1v;
            float v10 = acc[mt][n8][2] + b0v, v11 = acc[mt][n8][3] + b1v;
            if (Cf) {
                *(float2*)&Cf[(size_t)r0 * Nout + col] = make_float2(v00, v01);
                *(float2*)&Cf[(size_t)(r0 + 8) * Nout + col] = make_float2(v10, v11);
            }
            if (Chi) {
                uint32_t lp;
                uint32_t hp = split_pack(v00, v01, lp);
                *(uint32_t*)&Chi[(size_t)r0 * Nout + col] = hp;
                *(uint32_t*)&Clo[(size_t)r0 * Nout + col] = lp;
                hp = split_pack(v10, v11, lp);
                *(uint32_t*)&Chi[(size_t)(r0 + 8) * Nout + col] = hp;
                *(uint32_t*)&Clo[(size_t)(r0 + 8) * Nout + col] = lp;
            }
        }
    }
}

// ================= gate logits + sim =================
__global__ void __launch_bounds__(64)
gates_kernel(const float* __restrict__ Wgz, const float* __restrict__ bgz,
             const float* __restrict__ kvs, const float* __restrict__ qks) {
    const int idx = blockIdx.x;             // bh*L + l
    const int l = idx & (LL - 1);
    const int bh = idx >> 10;
    const int b = bh >> 3, hh = bh & 7;
    const size_t basei = ((size_t)(b * LL + l)) * DD + hh * HD;
    const float* kp = g_k + basei;
    const float* vp = g_v + basei;
    const float* qp = g_q + basei;
    const int j = threadIdx.x;

    float kj = kp[j];
    float w = 0.f;
#pragma unroll 8
    for (int i = 0; i < 64; ++i) w += vp[i] * Wgz[i * 64 + j];
    float p1 = w * kj;
    float p2 = qp[j] * kj;
#pragma unroll
    for (int off = 16; off; off >>= 1) {
        p1 += __shfl_down_sync(0xffffffffu, p1, off);
        p2 += __shfl_down_sync(0xffffffffu, p2, off);
    }
    __shared__ float r1[2], r2[2];
    if ((j & 31) == 0) { r1[j >> 5] = p1; r2[j >> 5] = p2; }
    __syncthreads();
    if (j == 0) {
        float s1 = r1[0] + r1[1], s2 = r2[0] + r2[1];
        float logit = kvs[0] * s1 + bgz[0];
        float o = (logit > 0.f) ? logit : 0.01f * logit;
        g_gates[idx] = o * o + EPSV;
        g_sim[idx] = s2 * qks[hh];
    }
}

// ================= inclusive scan of gates =================
__global__ void __launch_bounds__(LL)
scan_kernel() {
    __shared__ float s[LL];
    const int t = threadIdx.x;
    const int basei = blockIdx.x * LL;
    s[t] = g_gates[basei + t];
    __syncthreads();
#pragma unroll
    for (int off = 1; off < LL; off <<= 1) {
        float vv = (t >= off) ? s[t - off] : 0.f;
        __syncthreads();
        s[t] += vv;
        __syncthreads();
    }
    g_cumg[basei + t] = s[t];
}

// ================= causal linear attention + out gate (writes ao split) =================
__global__ void __launch_bounds__(256)
attn_kernel(const float* __restrict__ Wg, const float* __restrict__ bg,
            const float* __restrict__ kvs) {
    extern __shared__ float sm[];
    float* Qts = sm;
    float* Kts = Qts + 64 * 68;
    float* Vs  = Kts + 64 * 68;
    float* Sts = Vs  + 64 * 68;
    float* gsh = Sts + 64 * 68;

    const int bh = blockIdx.y;
    const int b = bh >> 3, hh = bh & 7;
    const int lb = blockIdx.x * 64;
    const int tx = threadIdx.x, ty = threadIdx.y;
    const int tid = ty * 16 + tx;

    for (int i = tid; i < 1024; i += 256) {
        int l = i >> 4, d4 = (i & 15) * 4;
        float4 qv = *(const float4*)&g_q[((size_t)(b * LL + lb + l)) * DD + hh * HD + d4];
        Qts[(d4 + 0) * 68 + l] = qv.x;
        Qts[(d4 + 1) * 68 + l] = qv.y;
        Qts[(d4 + 2) * 68 + l] = qv.z;
        Qts[(d4 + 3) * 68 + l] = qv.w;
    }

    float acc2[4][4];
#pragma unroll
    for (int r = 0; r < 4; ++r)
#pragma unroll
        for (int c = 0; c < 4; ++c) acc2[r][c] = 0.f;

    for (int t0 = 0; t0 <= lb; t0 += 64) {
        for (int i = tid; i < 1024; i += 256) {
            int t = i >> 4, d4 = (i & 15) * 4;
            size_t gidx = ((size_t)(b * LL + t0 + t)) * DD + hh * HD + d4;
            float4 kv = *(const float4*)&g_k[gidx];
            float4 vv = *(const float4*)&g_v[gidx];
            Kts[(d4 + 0) * 68 + t] = kv.x;
            Kts[(d4 + 1) * 68 + t] = kv.y;
            Kts[(d4 + 2) * 68 + t] = kv.z;
            Kts[(d4 + 3) * 68 + t] = kv.w;
            *(float4*)&Vs[t * 68 + d4] = vv;
        }
        if (tid < 64) gsh[tid] = g_gates[bh * LL + t0 + tid];
        __syncthreads();

        float acc1[4][4];
#pragma unroll
        for (int r = 0; r < 4; ++r)
#pragma unroll
            for (int c = 0; c < 4; ++c) acc1[r][c] = 0.f;
#pragma unroll 8
        for (int d = 0; d < 64; ++d) {
            float4 aq = *(float4*)&Qts[d * 68 + ty * 4];
            float4 ak = *(float4*)&Kts[d * 68 + tx * 4];
            float qa[4] = {aq.x, aq.y, aq.z, aq.w};
            float ka[4] = {ak.x, ak.y, ak.z, ak.w};
#pragma unroll
            for (int r = 0; r < 4; ++r)
#pragma unroll
                for (int c = 0; c < 4; ++c) acc1[r][c] += qa[r] * ka[c];
        }
#pragma unroll
        for (int c = 0; c < 4; ++c) {
            int tg = t0 + tx * 4 + c;
            float gg = gsh[tx * 4 + c];
#pragma unroll
            for (int r = 0; r < 4; ++r) {
                int lg = lb + ty * 4 + r;
                Sts[(tx * 4 + c) * 68 + ty * 4 + r] = (tg <= lg) ? acc1[r][c] * gg : 0.f;
            }
        }
        __syncthreads();
#pragma unroll 8
        for (int t = 0; t < 64; ++t) {
            float4 as = *(float4*)&Sts[t * 68 + ty * 4];
            float4 av = *(float4*)&Vs[t * 68 + tx * 4];
            float sa[4] = {as.x, as.y, as.z, as.w};
            float va[4] = {av.x, av.y, av.z, av.w};
#pragma unroll
            for (int r = 0; r < 4; ++r)
#pragma unroll
                for (int c = 0; c < 4; ++c) acc2[r][c] += sa[r] * va[c];
        }
        __syncthreads();
    }

    const float s = kvs[0];
#pragma unroll
    for (int r = 0; r < 4; ++r) {
        int lg = lb + ty * 4 + r;
        float cg = g_cumg[bh * LL + lg] + EPSV;
        float simv = g_sim[bh * LL + lg];
        float inv = s / cg;
        float oc[4];
#pragma unroll
        for (int c = 0; c < 4; ++c) {
            int ii = tx * 4 + c;
            float gate = 1.f / (1.f + expf(-(simv * Wg[ii] + bg[ii])));
            oc[c] = acc2[r][c] * inv * gate;
        }
        uint32_t l0, l1;
        uint32_t h0 = split_pack(oc[0], oc[1], l0);
        uint32_t h1 = split_pack(oc[2], oc[3], l1);
        size_t idx = ((size_t)(b * LL + lg)) * DD + hh * HD + tx * 4;
        *(uint2*)&g_ao_hi[idx] = make_uint2(h0, h1);
        *(uint2*)&g_ao_lo[idx] = make_uint2(l0, l1);
    }
}

// ================= launch =================
extern "C" void kernel_launch(void* const* d_in, const int* in_sizes, int n_in,
                              void* d_out, int out_size) {
    (void)in_sizes; (void)n_in; (void)out_size;
    const float* x     = (const float*)d_in[0];
    const float* basis = (const float*)d_in[1];
    const float* Wq    = (const float*)d_in[2];
    const float* bq    = (const float*)d_in[3];
    const float* Wk    = (const float*)d_in[4];
    const float* bk    = (const float*)d_in[5];
    const float* Wv    = (const float*)d_in[6];
    const float* bv    = (const float*)d_in[7];
    const float* Wo    = (const float*)d_in[8];
    const float* bo    = (const float*)d_in[9];
    const float* Wm    = (const float*)d_in[10];
    const float* bm    = (const float*)d_in[11];
    const float* Wgz   = (const float*)d_in[12];
    const float* bgz   = (const float*)d_in[13];
    const float* Wg    = (const float*)d_in[14];
    const float* bg    = (const float*)d_in[15];
    const float* kvs   = (const float*)d_in[16];
    const float* qks   = (const float*)d_in[17];

    cudaFuncSetAttribute(conv_mma, cudaFuncAttributeMaxDynamicSharedMemorySize, MMA_SMEM);
    cudaFuncSetAttribute(gemm_mma, cudaFuncAttributeMaxDynamicSharedMemorySize, MMA_SMEM);
    const int attn_smem = (4 * 64 * 68 + 64) * (int)sizeof(float);
    cudaFuncSetAttribute(attn_kernel, cudaFuncAttributeMaxDynamicSharedMemorySize, attn_smem);

    __nv_bfloat16 *xtch, *xtcl, *xTh, *xTl, *xh, *xl;
    __nv_bfloat16 *wmh, *wml, *wqh, *wql, *wkh, *wkl, *wvh, *wvl, *woh, *wol;
    __nv_bfloat16 *xth, *xtl, *aoh, *aol;
    float *q, *k, *v;
    cudaGetSymbolAddress((void**)&xtch, g_xtc_hi);
    cudaGetSymbolAddress((void**)&xtcl, g_xtc_lo);
    cudaGetSymbolAddress((void**)&xTh, g_xT_hi);
    cudaGetSymbolAddress((void**)&xTl, g_xT_lo);
    cudaGetSymbolAddress((void**)&xh, g_x_hi);
    cudaGetSymbolAddress((void**)&xl, g_x_lo);
    cudaGetSymbolAddress((void**)&wmh, g_WmT_hi);
    cudaGetSymbolAddress((void**)&wml, g_WmT_lo);
    cudaGetSymbolAddress((void**)&wqh, g_WqT_hi);
    cudaGetSymbolAddress((void**)&wql, g_WqT_lo);
    cudaGetSymbolAddress((void**)&wkh, g_WkT_hi);
    cudaGetSymbolAddress((void**)&wkl, g_WkT_lo);
    cudaGetSymbolAddress((void**)&wvh, g_WvT_hi);
    cudaGetSymbolAddress((void**)&wvl, g_WvT_lo);
    cudaGetSymbolAddress((void**)&woh, g_WoT_hi);
    cudaGetSymbolAddress((void**)&wol, g_WoT_lo);
    cudaGetSymbolAddress((void**)&xth, g_xt_hi);
    cudaGetSymbolAddress((void**)&xtl, g_xt_lo);
    cudaGetSymbolAddress((void**)&aoh, g_ao_hi);
    cudaGetSymbolAddress((void**)&aol, g_ao_lo);
    cudaGetSymbolAddress((void**)&q, g_q);
    cudaGetSymbolAddress((void**)&k, g_k);
    cudaGetSymbolAddress((void**)&v, g_v);

    dim3 tb(32, 8);

    // ---- preps ----
    trans_split<<<dim3(DD / 32, LL / 32, BB), tb>>>(x, xTh, xTl, LL, DD);   // x -> x^T
    split_only<<<(MM * DD + 255) / 256, 256>>>(x, xh, xl, MM * DD);
    trans_split<<<dim3(DD / 32, KD / 32, 1), tb>>>(Wm, wmh, wml, KD, DD);
    trans_split<<<dim3(DD / 32, DD / 32, 1), tb>>>(Wq, wqh, wql, DD, DD);
    trans_split<<<dim3(DD / 32, DD / 32, 1), tb>>>(Wk, wkh, wkl, DD, DD);
    trans_split<<<dim3(DD / 32, DD / 32, 1), tb>>>(Wv, wvh, wvl, DD, DD);
    trans_split<<<dim3(DD / 32, DD / 32, 1), tb>>>(Wo, woh, wol, DD, DD);
    toep_prep<<<KK * 32, 256>>>(basis);

    // ---- spectral conv (tensor cores) ----
    conv_mma<<<dim3(DD / 64, LL / 128, BB * KK), 256, MMA_SMEM>>>();

    // ---- xt = xtcat @ Wm + bm (split out) ----
    gemm_mma<<<dim3(DD / 64, MM / 128), 256, MMA_SMEM>>>(xtch, xtcl, wmh, wml, bm,
                                                         nullptr, xth, xtl, KD, DD);
    // ---- q / k / v ----
    gemm_mma<<<dim3(DD / 64, MM / 128), 256, MMA_SMEM>>>(xh, xl, wqh, wql, bq,
                                                         q, nullptr, nullptr, DD, DD);
    gemm_mma<<<dim3(DD / 64, MM / 128), 256, MMA_SMEM>>>(xth, xtl, wkh, wkl, bk,
                                                         k, nullptr, nullptr, DD, DD);
    gemm_mma<<<dim3(DD / 64, MM / 128), 256, MMA_SMEM>>>(xth, xtl, wvh, wvl, bv,
                                                         v, nullptr, nullptr, DD, DD);

    // ---- gates, scan, attention ----
    gates_kernel<<<BB * HH * LL, 64>>>(Wgz, bgz, kvs, qks);
    scan_kernel<<<BB * HH, LL>>>();
    attn_kernel<<<dim3(LL / 64, BB * HH), dim3(16, 16), attn_smem>>>(Wg, bg, kvs);

    // ---- out = ao @ Wo + bo ----
    gemm_mma<<<dim3(DD / 64, MM / 128), 256, MMA_SMEM>>>(aoh, aol, woh, wol, bo,
                                                         (float*)d_out, nullptr, nullptr, DD, DD);
}

// round 6
// speedup vs baseline: 2.0655x; 1.0026x over previous
#include <cuda_runtime.h>
#include <cuda_bf16.h>
#include <math.h>
#include <stdint.h>

#define BB 2
#define LL 1024
#define DD 512
#define HH 8
#define HD 64
#define KK 24
#define KD (KK*DD)   // 12288
#define MM (BB*LL)   // 2048
#define EPSV 1e-5f

// ================= scratch (static device globals; no allocation) =================
__device__ __nv_bfloat16 g_xtc_hi[(size_t)MM*KD];   // conv output hi (50 MB)
__device__ __nv_bfloat16 g_xtc_lo[(size_t)MM*KD];
__device__ __nv_bfloat16 g_toep_hi[(size_t)KK*32*4096];  // Toeplitz tile table
__device__ __nv_bfloat16 g_toep_lo[(size_t)KK*32*4096];
__device__ __nv_bfloat16 g_xT_hi[BB*DD*LL], g_xT_lo[BB*DD*LL];  // x^T (b,d,l)
__device__ __nv_bfloat16 g_x_hi[MM*DD],  g_x_lo[MM*DD];         // x row-major
__device__ __nv_bfloat16 g_WmT_hi[DD*KD], g_WmT_lo[DD*KD];
__device__ __nv_bfloat16 g_WqT_hi[DD*DD], g_WqT_lo[DD*DD];
__device__ __nv_bfloat16 g_WkT_hi[DD*DD], g_WkT_lo[DD*DD];
__device__ __nv_bfloat16 g_WvT_hi[DD*DD], g_WvT_lo[DD*DD];
__device__ __nv_bfloat16 g_WoT_hi[DD*DD], g_WoT_lo[DD*DD];
__device__ __nv_bfloat16 g_xt_hi[MM*DD], g_xt_lo[MM*DD];
__device__ __nv_bfloat16 g_ao_hi[MM*DD], g_ao_lo[MM*DD];
__device__ float g_q[MM*DD];
__device__ float g_k[MM*DD];
__device__ float g_v[MM*DD];
__device__ float g_gates[BB*HH*LL];
__device__ float g_cumg[BB*HH*LL];
__device__ float g_sim[BB*HH*LL];

// ================= PTX helpers (base ISA only: sm_80-class) =================
__device__ __forceinline__ uint32_t smem_u32(const void* p) {
    uint32_t a;
    asm("{ .reg .u64 t; cvta.to.shared.u64 t, %1; cvt.u32.u64 %0, t; }" : "=r"(a) : "l"(p));
    return a;
}
__device__ __forceinline__ void cp16(uint32_t dst, const void* src) {
    asm volatile("cp.async.cg.shared.global [%0], [%1], 16;" :: "r"(dst), "l"(src));
}
#define CP_COMMIT() asm volatile("cp.async.commit_group;" ::: "memory")
#define CP_WAIT(n)  asm volatile("cp.async.wait_group %0;" :: "n"(n) : "memory")

__device__ __forceinline__ void ldm4(uint32_t a, uint32_t r[4]) {
    asm volatile("ldmatrix.sync.aligned.m8n8.x4.shared.b16 {%0,%1,%2,%3}, [%4];"
                 : "=r"(r[0]), "=r"(r[1]), "=r"(r[2]), "=r"(r[3]) : "r"(a));
}
__device__ __forceinline__ void mma16816(float c[4], const uint32_t a[4], uint32_t b0, uint32_t b1) {
    asm volatile("mma.sync.aligned.m16n8k16.row.col.f32.bf16.bf16.f32 "
                 "{%0,%1,%2,%3}, {%4,%5,%6,%7}, {%8,%9}, {%0,%1,%2,%3};"
                 : "+f"(c[0]), "+f"(c[1]), "+f"(c[2]), "+f"(c[3])
                 : "r"(a[0]), "r"(a[1]), "r"(a[2]), "r"(a[3]), "r"(b0), "r"(b1));
}
__device__ __forceinline__ uint32_t split_pack(float f0, float f1, uint32_t& lopack) {
    __nv_bfloat16 h0 = __float2bfloat16(f0);
    __nv_bfloat16 h1 = __float2bfloat16(f1);
    __nv_bfloat16 l0 = __float2bfloat16(f0 - __bfloat162float(h0));
    __nv_bfloat16 l1 = __float2bfloat16(f1 - __bfloat162float(h1));
    lopack = (uint32_t)__bfloat16_as_ushort(l0) | ((uint32_t)__bfloat16_as_ushort(l1) << 16);
    return (uint32_t)__bfloat16_as_ushort(h0) | ((uint32_t)__bfloat16_as_ushort(h1) << 16);
}

// ---- smem layout per pipeline stage (BM=128, BN=64, BK=32, pad to 40 bf16/row) ----
#define ROWB 80           // bytes per padded row
#define OFF_AH 0
#define OFF_AL 10240
#define OFF_BH 20480
#define OFF_BL 25600
#define STG_BYTES 30720
#define MMA_SMEM (2*STG_BYTES)

// Load one stage: A 128x32 (hi+lo), B 64x32 (hi+lo). 256 threads.
__device__ __forceinline__ void load_stage(uint32_t sb,
        const __nv_bfloat16* Ah, const __nv_bfloat16* Al, size_t sA,
        const __nv_bfloat16* Bh, const __nv_bfloat16* Bl, size_t sB, int tid) {
#pragma unroll
    for (int i = 0; i < 2; ++i) {
        int idx = tid + i * 256;               // 0..511: A chunks
        int row = idx >> 2, c = idx & 3;
        uint32_t d = sb + (uint32_t)row * ROWB + (uint32_t)c * 16;
        cp16(d + OFF_AH, Ah + (size_t)row * sA + c * 8);
        cp16(d + OFF_AL, Al + (size_t)row * sA + c * 8);
    }
    {
        int row = tid >> 2, c = tid & 3;       // 256 B chunks
        uint32_t d = sb + (uint32_t)row * ROWB + (uint32_t)c * 16;
        cp16(d + OFF_BH, Bh + (size_t)row * sB + c * 8);
        cp16(d + OFF_BL, Bl + (size_t)row * sB + c * 8);
    }
}

// Compute one stage: 48 mma/warp (3-term split). Warp grid 4x2 (M x N), warp tile 32x32.
__device__ __forceinline__ void compute_stage(uint32_t sb, float acc[2][4][4],
                                              int wm, int wn, int lane) {
    const int t8 = lane & 7, sub = lane >> 3;
    const int arow = wm * 32 + (sub & 1) * 8 + t8;
    const int nrow = wn * 32 + (sub & 1) * 8 + t8;
    const int koff = (sub >> 1) * 8;
#pragma unroll
    for (int kh = 0; kh < 2; ++kh) {
        const int kc = kh * 16;
        uint32_t ah[2][4], al[2][4], bh[2][4], bl[2][4];
#pragma unroll
        for (int mt = 0; mt < 2; ++mt) {
            uint32_t off = (uint32_t)(arow + mt * 16) * ROWB + (uint32_t)(kc + koff) * 2;
            ldm4(sb + OFF_AH + off, ah[mt]);
            ldm4(sb + OFF_AL + off, al[mt]);
        }
#pragma unroll
        for (int nt = 0; nt < 2; ++nt) {
            uint32_t off = (uint32_t)(nrow + nt * 16) * ROWB + (uint32_t)(kc + koff) * 2;
            ldm4(sb + OFF_BH + off, bh[nt]);
            ldm4(sb + OFF_BL + off, bl[nt]);
        }
#pragma unroll
        for (int mt = 0; mt < 2; ++mt)
#pragma unroll
            for (int n8 = 0; n8 < 4; ++n8) {
                int nt = n8 >> 1, sl = n8 & 1;
                mma16816(acc[mt][n8], ah[mt], bh[nt][sl], bh[nt][sl + 2]);
                mma16816(acc[mt][n8], ah[mt], bl[nt][sl], bl[nt][sl + 2]);
                mma16816(acc[mt][n8], al[mt], bh[nt][sl], bh[nt][sl + 2]);
            }
    }
}

// ================= Toeplitz tile table precompute =================
// tile (kf, j): 128x32, A[r][c] = basis[r - c + (j-3)*32, kf] (0 if out of range)
__global__ void __launch_bounds__(256)
toep_prep(const float* __restrict__ basis) {
    int tile = blockIdx.x;                 // kf*32 + j
    int kf = tile >> 5, j = tile & 31;
    int d0 = (j - 3) * 32;
    size_t base = (size_t)tile * 4096;
    for (int idx = threadIdx.x; idx < 4096; idx += 256) {
        int r = idx >> 5, c = idx & 31;
        int off = r - c + d0;
        float v = (off >= 0 && off < LL) ? basis[off * KK + kf] : 0.f;
        __nv_bfloat16 h = __float2bfloat16(v);
        g_toep_hi[base + idx] = h;
        g_toep_lo[base + idx] = __float2bfloat16(v - __bfloat162float(h));
    }
}

// ================= prep kernels =================
__global__ void __launch_bounds__(256)
trans_split(const float* __restrict__ in, __nv_bfloat16* __restrict__ hi,
            __nv_bfloat16* __restrict__ lo, int R, int C) {
    __shared__ float t[32][33];
    int rb = blockIdx.y * 32, cb = blockIdx.x * 32, bz = blockIdx.z;
    const float* src = in + (size_t)bz * R * C;
    int tx = threadIdx.x, ty = threadIdx.y;   // (32, 8)
#pragma unroll
    for (int i = 0; i < 32; i += 8)
        t[ty + i][tx] = src[(size_t)(rb + ty + i) * C + cb + tx];
    __syncthreads();
    size_t ob = (size_t)bz * R * C;
#pragma unroll
    for (int i = 0; i < 32; i += 8) {
        float v = t[tx][ty + i];
        __nv_bfloat16 h = __float2bfloat16(v);
        size_t o = ob + (size_t)(cb + ty + i) * R + rb + tx;
        hi[o] = h;
        lo[o] = __float2bfloat16(v - __bfloat162float(h));
    }
}

__global__ void __launch_bounds__(256)
split_only(const float* __restrict__ in, __nv_bfloat16* __restrict__ hi,
           __nv_bfloat16* __restrict__ lo, int n) {
    int i = blockIdx.x * 256 + threadIdx.x;
    if (i < n) {
        float v = in[i];
        __nv_bfloat16 h = __float2bfloat16(v);
        hi[i] = h;
        lo[i] = __float2bfloat16(v - __bfloat162float(h));
    }
}

// ================= conv via mma.sync (Toeplitz-table GEMM) =================
// grid: (D/64, L/128, B*K). out[b*L+l, kf*D + d], split bf16.
__global__ void __launch_bounds__(256)
conv_mma() {
    extern __shared__ char dsm[];
    uint32_t sb0 = smem_u32(dsm);
    const int tid = threadIdx.x, wid = tid >> 5, lane = tid & 31;
    const int wm = wid >> 1, wn = wid & 1;
    const int db = blockIdx.x * 64;
    const int y = blockIdx.y, lb = y * 128;
    const int b = blockIdx.z / KK, kf = blockIdx.z % KK;
    const int nc = 4 * (y + 1);

    const __nv_bfloat16* xh = g_xT_hi + (size_t)b * DD * LL + (size_t)db * LL;
    const __nv_bfloat16* xl = g_xT_lo + (size_t)b * DD * LL + (size_t)db * LL;

    float acc[2][4][4];
#pragma unroll
    for (int a = 0; a < 2; ++a)
#pragma unroll
        for (int n = 0; n < 4; ++n)
#pragma unroll
            for (int e = 0; e < 4; ++e) acc[a][n][e] = 0.f;

    // chunk c: A tile = toep(kf, 4y - c + 3), B = xT cols t0 = 32c
    {
        size_t toff = ((size_t)(kf * 32 + 4 * y + 3)) * 4096;
        load_stage(sb0, g_toep_hi + toff, g_toep_lo + toff, 32, xh, xl, LL, tid);
        CP_COMMIT();
    }
    for (int c = 0; c < nc; ++c) {
        if (c + 1 < nc) {
            size_t toff = ((size_t)(kf * 32 + 4 * y - (c + 1) + 3)) * 4096;
            int t0 = 32 * (c + 1);
            load_stage(sb0 + ((c + 1) & 1) * STG_BYTES,
                       g_toep_hi + toff, g_toep_lo + toff, 32, xh + t0, xl + t0, LL, tid);
            CP_COMMIT();
            CP_WAIT(1);
        } else {
            CP_WAIT(0);
        }
        __syncthreads();
        compute_stage(sb0 + (c & 1) * STG_BYTES, acc, wm, wn, lane);
        __syncthreads();
    }

    // epilogue: split to hi/lo, 4B stores
    const int g = lane >> 2, tq = lane & 3;
#pragma unroll
    for (int mt = 0; mt < 2; ++mt) {
#pragma unroll
        for (int n8 = 0; n8 < 4; ++n8) {
            int col = db + wn * 32 + n8 * 8 + tq * 2;
            int r0 = lb + wm * 32 + mt * 16 + g;
            size_t o0 = (size_t)(b * LL + r0) * KD + (size_t)kf * DD + col;
            size_t o1 = o0 + 8 * (size_t)KD;
            uint32_t lp;
            uint32_t hp = split_pack(acc[mt][n8][0], acc[mt][n8][1], lp);
            *(uint32_t*)&g_xtc_hi[o0] = hp;  *(uint32_t*)&g_xtc_lo[o0] = lp;
            hp = split_pack(acc[mt][n8][2], acc[mt][n8][3], lp);
            *(uint32_t*)&g_xtc_hi[o1] = hp;  *(uint32_t*)&g_xtc_lo[o1] = lp;
        }
    }
}

// ================= generic split-bf16 GEMM via mma.sync =================
// C[m0+128, n0+64] = A[M,Kd] * B[Nout,Kd]^T + bias. grid (Nout/64, M/128).
__global__ void __launch_bounds__(256)
gemm_mma(const __nv_bfloat16* __restrict__ Ahi, const __nv_bfloat16* __restrict__ Alo,
         const __nv_bfloat16* __restrict__ Bhi, const __nv_bfloat16* __restrict__ Blo,
         const float* __restrict__ bias, float* __restrict__ Cf,
         __nv_bfloat16* __restrict__ Chi, __nv_bfloat16* __restrict__ Clo,
         int Kd, int Nout) {
    extern __shared__ char dsm[];
    uint32_t sb0 = smem_u32(dsm);
    const int tid = threadIdx.x, wid = tid >> 5, lane = tid & 31;
    const int wm = wid >> 1, wn = wid & 1;
    const int n0 = blockIdx.x * 64, m0 = blockIdx.y * 128;
    const int nc = Kd >> 5;

    const __nv_bfloat16* ah = Ahi + (size_t)m0 * Kd;
    const __nv_bfloat16* al = Alo + (size_t)m0 * Kd;
    const __nv_bfloat16* bh = Bhi + (size_t)n0 * Kd;
    const __nv_bfloat16* bl = Blo + (size_t)n0 * Kd;

    float acc[2][4][4];
#pragma unroll
    for (int a = 0; a < 2; ++a)
#pragma unroll
        for (int n = 0; n < 4; ++n)
#pragma unroll
            for (int e = 0; e < 4; ++e) acc[a][n][e] = 0.f;

    load_stage(sb0, ah, al, Kd, bh, bl, Kd, tid);
    CP_COMMIT();
    for (int c = 0; c < nc; ++c) {
        if (c + 1 < nc) {
            int k0 = 32 * (c + 1);
            load_stage(sb0 + ((c + 1) & 1) * STG_BYTES,
                       ah + k0, al + k0, Kd, bh + k0, bl + k0, Kd, tid);
            CP_COMMIT();
            CP_WAIT(1);
        } else {
            CP_WAIT(0);
        }
        __syncthreads();
        compute_stage(sb0 + (c & 1) * STG_BYTES, acc, wm, wn, lane);
        __syncthreads();
    }

    const int g = lane >> 2, tq = lane & 3;
#pragma unroll
    for (int mt = 0; mt < 2; ++mt) {
#pragma unroll
        for (int n8 = 0; n8 < 4; ++n8) {
            int col = n0 + wn * 32 + n8 * 8 + tq * 2;
            float b0v = bias[col], b1v = bias[col + 1];
            int r0 = m0 + wm * 32 + mt * 16 + g;
            float v00 = acc[mt][n8][0] + b0v, v01 = acc[mt][n8][1] + b1v;
            float v10 = acc[mt][n8][2] + b0v, v11 = acc[mt][n8][3] + b1v;
            if (Cf) {
                *(float2*)&Cf[(size_t)r0 * Nout + col] = make_float2(v00, v01);
                *(float2*)&Cf[(size_t)(r0 + 8) * Nout + col] = make_float2(v10, v11);
            }
            if (Chi) {
                uint32_t lp;
                uint32_t hp = split_pack(v00, v01, lp);
                *(uint32_t*)&Chi[(size_t)r0 * Nout + col] = hp;
                *(uint32_t*)&Clo[(size_t)r0 * Nout + col] = lp;
                hp = split_pack(v10, v11, lp);
                *(uint32_t*)&Chi[(size_t)(r0 + 8) * Nout + col] = hp;
                *(uint32_t*)&Clo[(size_t)(r0 + 8) * Nout + col] = lp;
            }
        }
    }
}

// ================= gate logits + sim =================
__global__ void __launch_bounds__(64)
gates_kernel(const float* __restrict__ Wgz, const float* __restrict__ bgz,
             const float* __restrict__ kvs, const float* __restrict__ qks) {
    const int idx = blockIdx.x;             // bh*L + l
    const int l = idx & (LL - 1);
    const int bh = idx >> 10;
    const int b = bh >> 3, hh = bh & 7;
    const size_t basei = ((size_t)(b * LL + l)) * DD + hh * HD;
    const float* kp = g_k + basei;
    const float* vp = g_v + basei;
    const float* qp = g_q + basei;
    const int j = threadIdx.x;

    float kj = kp[j];
    float w = 0.f;
#pragma unroll 8
    for (int i = 0; i < 64; ++i) w += vp[i] * Wgz[i * 64 + j];
    float p1 = w * kj;
    float p2 = qp[j] * kj;
#pragma unroll
    for (int off = 16; off; off >>= 1) {
        p1 += __shfl_down_sync(0xffffffffu, p1, off);
        p2 += __shfl_down_sync(0xffffffffu, p2, off);
    }
    __shared__ float r1[2], r2[2];
    if ((j & 31) == 0) { r1[j >> 5] = p1; r2[j >> 5] = p2; }
    __syncthreads();
    if (j == 0) {
        float s1 = r1[0] + r1[1], s2 = r2[0] + r2[1];
        float logit = kvs[0] * s1 + bgz[0];
        float o = (logit > 0.f) ? logit : 0.01f * logit;
        g_gates[idx] = o * o + EPSV;
        g_sim[idx] = s2 * qks[hh];
    }
}

// ================= inclusive scan of gates =================
__global__ void __launch_bounds__(LL)
scan_kernel() {
    __shared__ float s[LL];
    const int t = threadIdx.x;
    const int basei = blockIdx.x * LL;
    s[t] = g_gates[basei + t];
    __syncthreads();
#pragma unroll
    for (int off = 1; off < LL; off <<= 1) {
        float vv = (t >= off) ? s[t - off] : 0.f;
        __syncthreads();
        s[t] += vv;
        __syncthreads();
    }
    g_cumg[basei + t] = s[t];
}

// ================= causal linear attention + out gate (writes ao split) =================
__global__ void __launch_bounds__(256)
attn_kernel(const float* __restrict__ Wg, const float* __restrict__ bg,
            const float* __restrict__ kvs) {
    extern __shared__ float sm[];
    float* Qts = sm;
    float* Kts = Qts + 64 * 68;
    float* Vs  = Kts + 64 * 68;
    float* Sts = Vs  + 64 * 68;
    float* gsh = Sts + 64 * 68;

    const int bh = blockIdx.y;
    const int b = bh >> 3, hh = bh & 7;
    const int lb = blockIdx.x * 64;
    const int tx = threadIdx.x, ty = threadIdx.y;
    const int tid = ty * 16 + tx;

    for (int i = tid; i < 1024; i += 256) {
        int l = i >> 4, d4 = (i & 15) * 4;
        float4 qv = *(const float4*)&g_q[((size_t)(b * LL + lb + l)) * DD + hh * HD + d4];
        Qts[(d4 + 0) * 68 + l] = qv.x;
        Qts[(d4 + 1) * 68 + l] = qv.y;
        Qts[(d4 + 2) * 68 + l] = qv.z;
        Qts[(d4 + 3) * 68 + l] = qv.w;
    }

    float acc2[4][4];
#pragma unroll
    for (int r = 0; r < 4; ++r)
#pragma unroll
        for (int c = 0; c < 4; ++c) acc2[r][c] = 0.f;

    for (int t0 = 0; t0 <= lb; t0 += 64) {
        for (int i = tid; i < 1024; i += 256) {
            int t = i >> 4, d4 = (i & 15) * 4;
            size_t gidx = ((size_t)(b * LL + t0 + t)) * DD + hh * HD + d4;
            float4 kv = *(const float4*)&g_k[gidx];
            float4 vv = *(const float4*)&g_v[gidx];
            Kts[(d4 + 0) * 68 + t] = kv.x;
            Kts[(d4 + 1) * 68 + t] = kv.y;
            Kts[(d4 + 2) * 68 + t] = kv.z;
            Kts[(d4 + 3) * 68 + t] = kv.w;
            *(float4*)&Vs[t * 68 + d4] = vv;
        }
        if (tid < 64) gsh[tid] = g_gates[bh * LL + t0 + tid];
        __syncthreads();

        float acc1[4][4];
#pragma unroll
        for (int r = 0; r < 4; ++r)
#pragma unroll
            for (int c = 0; c < 4; ++c) acc1[r][c] = 0.f;
#pragma unroll 8
        for (int d = 0; d < 64; ++d) {
            float4 aq = *(float4*)&Qts[d * 68 + ty * 4];
            float4 ak = *(float4*)&Kts[d * 68 + tx * 4];
            float qa[4] = {aq.x, aq.y, aq.z, aq.w};
            float ka[4] = {ak.x, ak.y, ak.z, ak.w};
#pragma unroll
            for (int r = 0; r < 4; ++r)
#pragma unroll
                for (int c = 0; c < 4; ++c) acc1[r][c] += qa[r] * ka[c];
        }
#pragma unroll
        for (int c = 0; c < 4; ++c) {
            int tg = t0 + tx * 4 + c;
            float gg = gsh[tx * 4 + c];
#pragma unroll
            for (int r = 0; r < 4; ++r) {
                int lg = lb + ty * 4 + r;
                Sts[(tx * 4 + c) * 68 + ty * 4 + r] = (tg <= lg) ? acc1[r][c] * gg : 0.f;
            }
        }
        __syncthreads();
#pragma unroll 8
        for (int t = 0; t < 64; ++t) {
            float4 as = *(float4*)&Sts[t * 68 + ty * 4];
            float4 av = *(float4*)&Vs[t * 68 + tx * 4];
            float sa[4] = {as.x, as.y, as.z, as.w};
            float va[4] = {av.x, av.y, av.z, av.w};
#pragma unroll
            for (int r = 0; r < 4; ++r)
#pragma unroll
                for (int c = 0; c < 4; ++c) acc2[r][c] += sa[r] * va[c];
        }
        __syncthreads();
    }

    const float s = kvs[0];
#pragma unroll
    for (int r = 0; r < 4; ++r) {
        int lg = lb + ty * 4 + r;
        float cg = g_cumg[bh * LL + lg] + EPSV;
        float simv = g_sim[bh * LL + lg];
        float inv = s / cg;
        float oc[4];
#pragma unroll
        for (int c = 0; c < 4; ++c) {
            int ii = tx * 4 + c;
            float gate = 1.f / (1.f + expf(-(simv * Wg[ii] + bg[ii])));
            oc[c] = acc2[r][c] * inv * gate;
        }
        uint32_t l0, l1;
        uint32_t h0 = split_pack(oc[0], oc[1], l0);
        uint32_t h1 = split_pack(oc[2], oc[3], l1);
        size_t idx = ((size_t)(b * LL + lg)) * DD + hh * HD + tx * 4;
        *(uint2*)&g_ao_hi[idx] = make_uint2(h0, h1);
        *(uint2*)&g_ao_lo[idx] = make_uint2(l0, l1);
    }
}

// ================= launch =================
extern "C" void kernel_launch(void* const* d_in, const int* in_sizes, int n_in,
                              void* d_out, int out_size) {
    (void)in_sizes; (void)n_in; (void)out_size;
    const float* x     = (const float*)d_in[0];
    const float* basis = (const float*)d_in[1];
    const float* Wq    = (const float*)d_in[2];
    const float* bq    = (const float*)d_in[3];
    const float* Wk    = (const float*)d_in[4];
    const float* bk    = (const float*)d_in[5];
    const float* Wv    = (const float*)d_in[6];
    const float* bv    = (const float*)d_in[7];
    const float* Wo    = (const float*)d_in[8];
    const float* bo    = (const float*)d_in[9];
    const float* Wm    = (const float*)d_in[10];
    const float* bm    = (const float*)d_in[11];
    const float* Wgz   = (const float*)d_in[12];
    const float* bgz   = (const float*)d_in[13];
    const float* Wg    = (const float*)d_in[14];
    const float* bg    = (const float*)d_in[15];
    const float* kvs   = (const float*)d_in[16];
    const float* qks   = (const float*)d_in[17];

    cudaFuncSetAttribute(conv_mma, cudaFuncAttributeMaxDynamicSharedMemorySize, MMA_SMEM);
    cudaFuncSetAttribute(gemm_mma, cudaFuncAttributeMaxDynamicSharedMemorySize, MMA_SMEM);
    const int attn_smem = (4 * 64 * 68 + 64) * (int)sizeof(float);
    cudaFuncSetAttribute(attn_kernel, cudaFuncAttributeMaxDynamicSharedMemorySize, attn_smem);

    __nv_bfloat16 *xtch, *xtcl, *xTh, *xTl, *xh, *xl;
    __nv_bfloat16 *wmh, *wml, *wqh, *wql, *wkh, *wkl, *wvh, *wvl, *woh, *wol;
    __nv_bfloat16 *xth, *xtl, *aoh, *aol;
    float *q, *k, *v;
    cudaGetSymbolAddress((void**)&xtch, g_xtc_hi);
    cudaGetSymbolAddress((void**)&xtcl, g_xtc_lo);
    cudaGetSymbolAddress((void**)&xTh, g_xT_hi);
    cudaGetSymbolAddress((void**)&xTl, g_xT_lo);
    cudaGetSymbolAddress((void**)&xh, g_x_hi);
    cudaGetSymbolAddress((void**)&xl, g_x_lo);
    cudaGetSymbolAddress((void**)&wmh, g_WmT_hi);
    cudaGetSymbolAddress((void**)&wml, g_WmT_lo);
    cudaGetSymbolAddress((void**)&wqh, g_WqT_hi);
    cudaGetSymbolAddress((void**)&wql, g_WqT_lo);
    cudaGetSymbolAddress((void**)&wkh, g_WkT_hi);
    cudaGetSymbolAddress((void**)&wkl, g_WkT_lo);
    cudaGetSymbolAddress((void**)&wvh, g_WvT_hi);
    cudaGetSymbolAddress((void**)&wvl, g_WvT_lo);
    cudaGetSymbolAddress((void**)&woh, g_WoT_hi);
    cudaGetSymbolAddress((void**)&wol, g_WoT_lo);
    cudaGetSymbolAddress((void**)&xth, g_xt_hi);
    cudaGetSymbolAddress((void**)&xtl, g_xt_lo);
    cudaGetSymbolAddress((void**)&aoh, g_ao_hi);
    cudaGetSymbolAddress((void**)&aol, g_ao_lo);
    cudaGetSymbolAddress((void**)&q, g_q);
    cudaGetSymbolAddress((void**)&k, g_k);
    cudaGetSymbolAddress((void**)&v, g_v);

    dim3 tb(32, 8);

    // ---- preps ----
    trans_split<<<dim3(DD / 32, LL / 32, BB), tb>>>(x, xTh, xTl, LL, DD);   // x -> x^T
    split_only<<<(MM * DD + 255) / 256, 256>>>(x, xh, xl, MM * DD);
    trans_split<<<dim3(DD / 32, KD / 32, 1), tb>>>(Wm, wmh, wml, KD, DD);
    trans_split<<<dim3(DD / 32, DD / 32, 1), tb>>>(Wq, wqh, wql, DD, DD);
    trans_split<<<dim3(DD / 32, DD / 32, 1), tb>>>(Wk, wkh, wkl, DD, DD);
    trans_split<<<dim3(DD / 32, DD / 32, 1), tb>>>(Wv, wvh, wvl, DD, DD);
    trans_split<<<dim3(DD / 32, DD / 32, 1), tb>>>(Wo, woh, wol, DD, DD);
    toep_prep<<<KK * 32, 256>>>(basis);

    // ---- spectral conv (tensor cores) ----
    conv_mma<<<dim3(DD / 64, LL / 128, BB * KK), 256, MMA_SMEM>>>();

    // ---- xt = xtcat @ Wm + bm (split out) ----
    gemm_mma<<<dim3(DD / 64, MM / 128), 256, MMA_SMEM>>>(xtch, xtcl, wmh, wml, bm,
                                                         nullptr, xth, xtl, KD, DD);
    // ---- q / k / v ----
    gemm_mma<<<dim3(DD / 64, MM / 128), 256, MMA_SMEM>>>(xh, xl, wqh, wql, bq,
                                                         q, nullptr, nullptr, DD, DD);
    gemm_mma<<<dim3(DD / 64, MM / 128), 256, MMA_SMEM>>>(xth, xtl, wkh, wkl, bk,
                                                         k, nullptr, nullptr, DD, DD);
    gemm_mma<<<dim3(DD / 64, MM / 128), 256, MMA_SMEM>>>(xth, xtl, wvh, wvl, bv,
                                                         v, nullptr, nullptr, DD, DD);

    // ---- gates, scan, attention ----
    gates_kernel<<<BB * HH * LL, 64>>>(Wgz, bgz, kvs, qks);
    scan_kernel<<<BB * HH, LL>>>();
    attn_kernel<<<dim3(LL / 64, BB * HH), dim3(16, 16), attn_smem>>>(Wg, bg, kvs);

    // ---- out = ao @ Wo + bo ----
    gemm_mma<<<dim3(DD / 64, MM / 128), 256, MMA_SMEM>>>(aoh, aol, woh, wol, bo,
                                                         (float*)d_out, nullptr, nullptr, DD, DD);
}